// round 16
// baseline (speedup 1.0000x reference)
#include <cuda_runtime.h>
#include <cuda_bf16.h>
#include <math.h>
#include <stdint.h>

// ---------------------------------------------------------------------------
// ChunkedCrossAttention (B=4,S=1024,D=1024,H=16,Dk=64,CL=64,N=2,NL=128)
// Dual GEMM variants: 512-thr (throughput, KV) + 256-thr 64x64-tile
// (latency, single-wave Q and O). R13 topology otherwise.
// ---------------------------------------------------------------------------

typedef __nv_bfloat16  bf16;
typedef __nv_bfloat162 bf162;

__device__ bf16 g_ebf[16u*1024*1024];
__device__ bf16 g_wqt[1024*1024];          // [n][k]
__device__ bf16 g_wkv[2u*1024*1024];       // [n][k]: rows 0-1023 Wk^T, 1024-2047 Wv^T
__device__ bf16 g_wot[1024*1024];          // [n][k]
__device__ bf16 g_hnb[4u*1024*1024];
__device__ bf16 g_qb [4u*1024*1024];
__device__ bf16 g_kb [16u*1024*1024];
__device__ bf16 g_vb [16u*1024*1024];
__device__ bf16 g_aob[4u*1024*1024];

__device__ __forceinline__ unsigned smaddr(const void* p) {
    return (unsigned)__cvta_generic_to_shared(p);
}
__device__ __forceinline__ void cp16(uint32_t dst, const void* src) {
    asm volatile("cp.async.cg.shared.global [%0], [%1], 16;" :: "r"(dst), "l"(src));
}
#define CP_COMMIT() asm volatile("cp.async.commit_group;" ::: "memory")
#define CP_WAIT(n)  asm volatile("cp.async.wait_group %0;" :: "n"(n) : "memory")

__device__ __forceinline__ void ldsm_x4(unsigned* r, unsigned addr) {
    asm volatile("ldmatrix.sync.aligned.m8n8.x4.shared.b16 {%0,%1,%2,%3}, [%4];"
        : "=r"(r[0]), "=r"(r[1]), "=r"(r[2]), "=r"(r[3]) : "r"(addr));
}
__device__ __forceinline__ void ldsm_x4_t(unsigned* r, unsigned addr) {
    asm volatile("ldmatrix.sync.aligned.m8n8.x4.trans.shared.b16 {%0,%1,%2,%3}, [%4];"
        : "=r"(r[0]), "=r"(r[1]), "=r"(r[2]), "=r"(r[3]) : "r"(addr));
}
__device__ __forceinline__ void mma_bf16(float* c, const unsigned* a, const unsigned* b) {
    asm volatile(
        "mma.sync.aligned.m16n8k16.row.col.f32.bf16.bf16.f32 "
        "{%0,%1,%2,%3}, {%4,%5,%6,%7}, {%8,%9}, {%0,%1,%2,%3};\n"
        : "+f"(c[0]), "+f"(c[1]), "+f"(c[2]), "+f"(c[3])
        : "r"(a[0]), "r"(a[1]), "r"(a[2]), "r"(a[3]), "r"(b[0]), "r"(b[1]));
}

// ---------------------------------------------------------------------------
__global__ __launch_bounds__(256)
void f2bf(const float4* __restrict__ src, bf162* __restrict__ dst, int n4)
{
    int i = blockIdx.x * blockDim.x + threadIdx.x;
    if (i < n4) {
        float4 v = src[i];
        dst[2*i]     = __floats2bfloat162_rn(v.x, v.y);
        dst[2*i + 1] = __floats2bfloat162_rn(v.z, v.w);
    }
}

__global__ __launch_bounds__(256)
void f2bf_T4(const float* __restrict__ W0, const float* __restrict__ W1,
             const float* __restrict__ W2, const float* __restrict__ W3,
             bf16* __restrict__ D0, bf16* __restrict__ D1,
             bf16* __restrict__ D2, bf16* __restrict__ D3)
{
    const float* W; bf16* D;
    switch (blockIdx.z) {
        case 0:  W = W0; D = D0; break;
        case 1:  W = W1; D = D1; break;
        case 2:  W = W2; D = D2; break;
        default: W = W3; D = D3; break;
    }
    __shared__ float t[32][33];
    const int tx = threadIdx.x & 31, ty = threadIdx.x >> 5;
    const int n0 = blockIdx.x * 32, k0 = blockIdx.y * 32;
    #pragma unroll
    for (int i = 0; i < 4; ++i)
        t[ty + 8*i][tx] = W[(size_t)(k0 + ty + 8*i) * 1024 + n0 + tx];
    __syncthreads();
    #pragma unroll
    for (int i = 0; i < 4; ++i)
        D[(size_t)(n0 + ty + 8*i) * 1024 + k0 + tx] = __float2bfloat16(t[tx][ty + 8*i]);
}

__global__ __launch_bounds__(256)
void copy_prefix(const float4* __restrict__ h, float4* __restrict__ out)
{
    int i = blockIdx.x * blockDim.x + threadIdx.x;
    if (i < 4 * 16128) {
        int b = i / 16128, r = i - b * 16128;
        out[(size_t)b * 262144 + r] = h[(size_t)b * 262144 + r];
    }
}

// ---------------------------------------------------------------------------
__global__ __launch_bounds__(256)
void rmsnorm_bf16(const float* __restrict__ h, const float* __restrict__ g,
                  bf16* __restrict__ hn)
{
    const int row = blockIdx.x;
    const int b = row >> 10, p = row & 1023;
    const int t = threadIdx.x;
    bf162* dst = reinterpret_cast<bf162*>(hn + (size_t)row * 1024);
    if (p >= 961) {
        bf162 z = __floats2bfloat162_rn(0.f, 0.f);
        dst[2*t] = z; dst[2*t + 1] = z;
        return;
    }
    const float4* src = reinterpret_cast<const float4*>(h + ((size_t)(b*1024 + p + 63)) * 1024);
    float4 x = src[t];
    float s = x.x*x.x + x.y*x.y + x.z*x.z + x.w*x.w;
    #pragma unroll
    for (int o = 16; o; o >>= 1) s += __shfl_xor_sync(0xffffffffu, s, o);
    __shared__ float red[8];
    if ((t & 31) == 0) red[t >> 5] = s;
    __syncthreads();
    float total = red[0]+red[1]+red[2]+red[3]+red[4]+red[5]+red[6]+red[7];
    float inv = rsqrtf(total * (1.f/1024.f) + 1e-8f);
    float4 gg = reinterpret_cast<const float4*>(g)[t];
    dst[2*t]     = __floats2bfloat162_rn(x.x*gg.x*inv, x.y*gg.y*inv);
    dst[2*t + 1] = __floats2bfloat162_rn(x.z*gg.z*inv, x.w*gg.w*inv);
}

// ---------------------------------------------------------------------------
// Throughput GEMM (KV): 512 thr = 16 warps (4m x 4n), warp tile 32x64.
// Block 128x256, BK=32, 6-stage cp.async ring. Proven 186us @ 7 waves.
// mode 0 split store only (KV always mode 0).
// ---------------------------------------------------------------------------
#define GEMM_SMEM (6 * 24576)

__global__ __launch_bounds__(512, 1)
void gemm_512(const bf16* __restrict__ A, const bf16* __restrict__ Bt,
              const float* __restrict__ bias1, const float* __restrict__ bias2,
              bf16* __restrict__ C1, bf16* __restrict__ C2)
{
    extern __shared__ char dyn[];
    const uint32_t sbase = smaddr(dyn);

    const int tid = threadIdx.x, lane = tid & 31, warp = tid >> 5;
    const int bm = blockIdx.y * 128, bn = blockIdx.x * 256;
    const int wm = (warp >> 2) * 32, wn = (warp & 3) * 64;

    const uint32_t ar = tid >> 2, ag = tid & 3;
    const uint32_t aoff = ar * 64 + ((ag ^ ((ar >> 1) & 3)) << 4);
    const bf16* asrc = A + (size_t)(bm + ar) * 1024 + ag * 8;
    uint32_t boff[2]; const bf16* bsrc[2];
    #pragma unroll
    for (int i = 0; i < 2; ++i) {
        uint32_t c = tid + i * 512, r = c >> 2, g = c & 3;
        boff[i] = 8192 + r * 64 + ((g ^ ((r >> 1) & 3)) << 4);
        bsrc[i] = Bt + (size_t)(bn + r) * 1024 + g * 8;
    }

    const uint32_t a_row = wm + (lane & 15);
    const uint32_t a_base = sbase + a_row * 64;
    const uint32_t a_sw = (a_row >> 1) & 3;
    const uint32_t ga0 = lane >> 4;
    const uint32_t b_row = wn + (lane & 7) + ((lane >> 4) & 1) * 8;
    const uint32_t b_base = sbase + 8192 + b_row * 64;
    const uint32_t b_sw = (b_row >> 1) & 3;
    const uint32_t gb0 = (lane >> 3) & 1;

    float acc[2][8][4];
    #pragma unroll
    for (int a = 0; a < 2; ++a)
        #pragma unroll
        for (int b = 0; b < 8; ++b)
            #pragma unroll
            for (int q = 0; q < 4; ++q) acc[a][b][q] = 0.f;

#define LOAD_STAGE(S, KT) do { \
    cp16(sbase + (uint32_t)(S)*24576u + aoff,    asrc    + (KT)*32); \
    cp16(sbase + (uint32_t)(S)*24576u + boff[0], bsrc[0] + (KT)*32); \
    cp16(sbase + (uint32_t)(S)*24576u + boff[1], bsrc[1] + (KT)*32); \
    CP_COMMIT(); \
} while(0)

#define COMPUTE_STAGE(S) do { \
    const uint32_t _ab = a_base + (uint32_t)(S)*24576u; \
    const uint32_t _bb = b_base + (uint32_t)(S)*24576u; \
    _Pragma("unroll") \
    for (int ks = 0; ks < 2; ++ks) { \
        unsigned af[2][4]; \
        _Pragma("unroll") \
        for (int mt = 0; mt < 2; ++mt) \
            ldsm_x4(af[mt], _ab + mt*1024 + (((ga0 + ks*2) ^ a_sw) << 4)); \
        unsigned bq[4][4]; \
        _Pragma("unroll") \
        for (int nt = 0; nt < 4; ++nt) \
            ldsm_x4(bq[nt], _bb + nt*1024 + (((gb0 + ks*2) ^ b_sw) << 4)); \
        _Pragma("unroll") \
        for (int mt = 0; mt < 2; ++mt) \
            _Pragma("unroll") \
            for (int nt = 0; nt < 4; ++nt) { \
                mma_bf16(acc[mt][nt*2],     af[mt], bq[nt]); \
                mma_bf16(acc[mt][nt*2 + 1], af[mt], bq[nt] + 2); \
            } \
    } \
} while(0)

    #pragma unroll
    for (int s = 0; s < 4; ++s) LOAD_STAGE(s, s);

    int s0 = 0;
    for (int kt = 0; kt < 32; kt += 2) {
        if (kt < 30) { CP_WAIT(2); } else { CP_WAIT(0); }
        __syncthreads();
        const int s1 = (s0 + 1 == 6) ? 0 : s0 + 1;
        COMPUTE_STAGE(s0);
        COMPUTE_STAGE(s1);
        if (kt + 4 < 32) {
            int s4 = s0 + 4; if (s4 >= 6) s4 -= 6;
            LOAD_STAGE(s4, kt + 4);
        }
        if (kt + 5 < 32) {
            int s5 = s0 + 5; if (s5 >= 6) s5 -= 6;
            LOAD_STAGE(s5, kt + 5);
        }
        s0 += 2; if (s0 >= 6) s0 -= 6;
    }

    #pragma unroll
    for (int mt = 0; mt < 2; ++mt) {
        #pragma unroll
        for (int j = 0; j < 8; ++j) {
            const int row  = bm + wm + mt * 16 + (lane >> 2);
            const int gcol = bn + wn + (j >> 1) * 16 + (j & 1) * 8 + (lane & 3) * 2;
            const float* bb = bias1; bf16* dst = C1; int cc = gcol;
            if (gcol >= 1024) { bb = bias2; dst = C2; cc = gcol - 1024; }
            const float b0 = bb[cc], b1 = bb[cc + 1];
            *(bf162*)(dst + (size_t)row * 1024 + cc) =
                __floats2bfloat162_rn(acc[mt][j][0] + b0, acc[mt][j][1] + b1);
            *(bf162*)(dst + (size_t)(row + 8) * 1024 + cc) =
                __floats2bfloat162_rn(acc[mt][j][2] + b0, acc[mt][j][3] + b1);
        }
    }
#undef LOAD_STAGE
#undef COMPUTE_STAGE
}

// ---------------------------------------------------------------------------
// Latency GEMM (Q, O): 256 thr = 8 warps (2m x 4n), warp tile 64x64.
// Single-wave grids: per-block latency = kernel duration; measured 29 vs 32us.
// mode 0: bf16 store to C1; mode 1: residual write Cf[row+63]=Hres+acc+bias1.
// ---------------------------------------------------------------------------
__global__ __launch_bounds__(256, 1)
void gemm_256(const bf16* __restrict__ A, const bf16* __restrict__ Bt,
              const float* __restrict__ bias1,
              bf16* __restrict__ C1,
              float* __restrict__ Cf, const float* __restrict__ Hres, int mode)
{
    extern __shared__ char dyn[];
    const uint32_t sbase = smaddr(dyn);

    const int tid = threadIdx.x, lane = tid & 31, warp = tid >> 5;
    const int bm = blockIdx.y * 128, bn = blockIdx.x * 256;
    const int wm = (warp >> 2) * 64, wn = (warp & 3) * 64;

    uint32_t aoff[2]; const bf16* asrc[2];
    #pragma unroll
    for (int i = 0; i < 2; ++i) {
        uint32_t c = tid + i * 256, r = c >> 2, g = c & 3;
        aoff[i] = r * 64 + ((g ^ ((r >> 1) & 3)) << 4);
        asrc[i] = A + (size_t)(bm + r) * 1024 + g * 8;
    }
    uint32_t boff[4]; const bf16* bsrc[4];
    #pragma unroll
    for (int i = 0; i < 4; ++i) {
        uint32_t c = tid + i * 256, r = c >> 2, g = c & 3;
        boff[i] = 8192 + r * 64 + ((g ^ ((r >> 1) & 3)) << 4);
        bsrc[i] = Bt + (size_t)(bn + r) * 1024 + g * 8;
    }

    const uint32_t a_row = wm + (lane & 15);
    const uint32_t a_base = sbase + a_row * 64;
    const uint32_t a_sw = (a_row >> 1) & 3;
    const uint32_t ga0 = lane >> 4;
    const uint32_t b_row = wn + (lane & 7) + ((lane >> 4) & 1) * 8;
    const uint32_t b_base = sbase + 8192 + b_row * 64;
    const uint32_t b_sw = (b_row >> 1) & 3;
    const uint32_t gb0 = (lane >> 3) & 1;

    float acc[4][8][4];
    #pragma unroll
    for (int a = 0; a < 4; ++a)
        #pragma unroll
        for (int b = 0; b < 8; ++b)
            #pragma unroll
            for (int q = 0; q < 4; ++q) acc[a][b][q] = 0.f;

#define LOAD_STAGE(S, KT) do { \
    cp16(sbase + (uint32_t)(S)*24576u + aoff[0], asrc[0] + (KT)*32); \
    cp16(sbase + (uint32_t)(S)*24576u + aoff[1], asrc[1] + (KT)*32); \
    cp16(sbase + (uint32_t)(S)*24576u + boff[0], bsrc[0] + (KT)*32); \
    cp16(sbase + (uint32_t)(S)*24576u + boff[1], bsrc[1] + (KT)*32); \
    cp16(sbase + (uint32_t)(S)*24576u + boff[2], bsrc[2] + (KT)*32); \
    cp16(sbase + (uint32_t)(S)*24576u + boff[3], bsrc[3] + (KT)*32); \
    CP_COMMIT(); \
} while(0)

#define COMPUTE_STAGE(S) do { \
    const uint32_t _ab = a_base + (uint32_t)(S)*24576u; \
    const uint32_t _bb = b_base + (uint32_t)(S)*24576u; \
    _Pragma("unroll") \
    for (int ks = 0; ks < 2; ++ks) { \
        unsigned bq[4][4]; \
        _Pragma("unroll") \
        for (int nt = 0; nt < 4; ++nt) \
            ldsm_x4(bq[nt], _bb + nt*1024 + (((gb0 + ks*2) ^ b_sw) << 4)); \
        _Pragma("unroll") \
        for (int mt = 0; mt < 4; ++mt) { \
            unsigned af[4]; \
            ldsm_x4(af, _ab + mt*1024 + (((ga0 + ks*2) ^ a_sw) << 4)); \
            _Pragma("unroll") \
            for (int nt = 0; nt < 4; ++nt) { \
                mma_bf16(acc[mt][nt*2],     af, bq[nt]); \
                mma_bf16(acc[mt][nt*2 + 1], af, bq[nt] + 2); \
            } \
        } \
    } \
} while(0)

    #pragma unroll
    for (int s = 0; s < 4; ++s) LOAD_STAGE(s, s);

    int s0 = 0;
    for (int kt = 0; kt < 32; kt += 2) {
        if (kt < 30) { CP_WAIT(2); } else { CP_WAIT(0); }
        __syncthreads();
        const int s1 = (s0 + 1 == 6) ? 0 : s0 + 1;
        COMPUTE_STAGE(s0);
        COMPUTE_STAGE(s1);
        if (kt + 4 < 32) {
            int s4 = s0 + 4; if (s4 >= 6) s4 -= 6;
            LOAD_STAGE(s4, kt + 4);
        }
        if (kt + 5 < 32) {
            int s5 = s0 + 5; if (s5 >= 6) s5 -= 6;
            LOAD_STAGE(s5, kt + 5);
        }
        s0 += 2; if (s0 >= 6) s0 -= 6;
    }

    #pragma unroll
    for (int mt = 0; mt < 4; ++mt) {
        #pragma unroll
        for (int j = 0; j < 8; ++j) {
            const int row  = bm + wm + mt * 16 + (lane >> 2);
            const int gcol = bn + wn + (j >> 1) * 16 + (j & 1) * 8 + (lane & 3) * 2;
            if (mode == 0) {
                const float b0 = bias1[gcol], b1 = bias1[gcol + 1];
                *(bf162*)(C1 + (size_t)row * 1024 + gcol) =
                    __floats2bfloat162_rn(acc[mt][j][0] + b0, acc[mt][j][1] + b1);
                *(bf162*)(C1 + (size_t)(row + 8) * 1024 + gcol) =
                    __floats2bfloat162_rn(acc[mt][j][2] + b0, acc[mt][j][3] + b1);
            } else {
                const float b0 = bias1[gcol], b1 = bias1[gcol + 1];
                const int p = row & 1023;
                if (p < 961) {
                    const size_t o = (size_t)(row + 63) * 1024 + gcol;
                    Cf[o]     = Hres[o]     + acc[mt][j][0] + b0;
                    Cf[o + 1] = Hres[o + 1] + acc[mt][j][1] + b1;
                }
                const int p2 = (row + 8) & 1023;
                if (p2 < 961) {
                    const size_t o = (size_t)(row + 71) * 1024 + gcol;
                    Cf[o]     = Hres[o]     + acc[mt][j][2] + b0;
                    Cf[o + 1] = Hres[o + 1] + acc[mt][j][3] + b1;
                }
            }
        }
    }
#undef LOAD_STAGE
#undef COMPUTE_STAGE
}

// ---------------------------------------------------------------------------
// Attention per (b, chunk, head): 256 threads = 8 warps (2m x 4n).
// Register logits + distributed softmax; P overwrites K slot -> 74KB, 3 CTA/SM.
// ---------------------------------------------------------------------------
#define ATTN_SMEM_BYTES 75776

__global__ __launch_bounds__(256, 3)
void attn_bf16(const bf16* __restrict__ Q, const bf16* __restrict__ K,
               const bf16* __restrict__ V, bf16* __restrict__ AO)
{
    extern __shared__ char smraw[];
    const uint32_t sb = smaddr(smraw);
    const uint32_t qb = sb, kb = sb + 8192, vb = sb + 40960, pb = sb + 8192;
    float* red_max = reinterpret_cast<float*>(smraw + 73728);
    float* red_sum = reinterpret_cast<float*>(smraw + 74752);

    const int bid = blockIdx.x;
    const int b  = bid >> 8, c = (bid >> 4) & 15, hh = bid & 15;
    const int tid = threadIdx.x, lane = tid & 31, warp = tid >> 5;

    const size_t qbase  = ((size_t)(b * 1024 + c * 64)) * 1024 + hh * 64;
    const size_t kvbase = ((size_t)((b * 16 + c) * 256)) * 1024 + hh * 64;

    #pragma unroll
    for (int i = 0; i < 2; ++i) {
        int ch = tid + i * 256, r = ch >> 3, sg = ch & 7;
        uint32_t off = r * 128 + (((uint32_t)sg << 4) ^ (((uint32_t)(r & 7)) << 4));
        *(uint4*)(smraw + off) = *(const uint4*)(Q + qbase + (size_t)r * 1024 + sg * 8);
    }
    #pragma unroll
    for (int i = 0; i < 8; ++i) {
        int ch = tid + i * 256, r = ch >> 3, sg = ch & 7;
        uint32_t off = r * 128 + (((uint32_t)sg << 4) ^ (((uint32_t)(r & 7)) << 4));
        *(uint4*)(smraw + 8192 + off)  = *(const uint4*)(K + kvbase + (size_t)r * 1024 + sg * 8);
        *(uint4*)(smraw + 40960 + off) = *(const uint4*)(V + kvbase + (size_t)r * 1024 + sg * 8);
    }
    __syncthreads();

    const int wm  = (warp >> 2) * 32;
    const uint32_t xr = ((uint32_t)(lane & 7)) << 4;

    float acc[2][8][4];
    #pragma unroll
    for (int i = 0; i < 2; i++)
        #pragma unroll
        for (int j = 0; j < 8; j++)
            #pragma unroll
            for (int q = 0; q < 4; q++) acc[i][j][q] = 0.f;

    {
        const int wnl = (warp & 3) * 64;
        const uint32_t qrow = qb + (wm + (lane & 15)) * 128;
        const uint32_t krow = kb + (wnl + (lane & 7) + ((lane >> 4) & 1) * 8) * 128;

        #pragma unroll
        for (int ks = 0; ks < 4; ++ks) {
            const uint32_t gq = (uint32_t)((lane >> 4) + ks * 2) << 4;
            unsigned af[2][4];
            ldsm_x4(af[0], qrow + (gq ^ xr));
            ldsm_x4(af[1], qrow + 16*128 + (gq ^ xr));
            const uint32_t gk = (uint32_t)(((lane >> 3) & 1) + ks * 2) << 4;
            #pragma unroll
            for (int nt = 0; nt < 4; ++nt) {
                unsigned bq[4];
                ldsm_x4(bq, krow + nt*16*128 + (gk ^ xr));
                mma_bf16(acc[0][nt*2],     af[0], bq);
                mma_bf16(acc[0][nt*2 + 1], af[0], bq + 2);
                mma_bf16(acc[1][nt*2],     af[1], bq);
                mma_bf16(acc[1][nt*2 + 1], af[1], bq + 2);
            }
        }
    }

    #pragma unroll
    for (int i = 0; i < 2; i++)
        #pragma unroll
        for (int j = 0; j < 8; j++)
            #pragma unroll
            for (int q = 0; q < 4; q++) acc[i][j][q] *= 0.125f;

    const int rloc0 = wm + (lane >> 2);
    {
        #pragma unroll
        for (int mt = 0; mt < 2; ++mt)
            #pragma unroll
            for (int hf = 0; hf < 2; ++hf) {
                float m = -1e30f;
                #pragma unroll
                for (int nt = 0; nt < 8; ++nt)
                    m = fmaxf(m, fmaxf(acc[mt][nt][hf*2], acc[mt][nt][hf*2 + 1]));
                m = fmaxf(m, __shfl_xor_sync(0xffffffffu, m, 1));
                m = fmaxf(m, __shfl_xor_sync(0xffffffffu, m, 2));
                if ((lane & 3) == 0)
                    red_max[(warp & 3) * 64 + rloc0 + mt*16 + hf*8] = m;
            }
    }
    __syncthreads();
    {
        #pragma unroll
        for (int mt = 0; mt < 2; ++mt)
            #pragma unroll
            for (int hf = 0; hf < 2; ++hf) {
                const int row = rloc0 + mt*16 + hf*8;
                const float gm = fmaxf(fmaxf(red_max[row], red_max[64 + row]),
                                       fmaxf(red_max[128 + row], red_max[192 + row]));
                float s = 0.f;
                #pragma unroll
                for (int nt = 0; nt < 8; ++nt) {
                    float e0 = __expf(acc[mt][nt][hf*2]     - gm);
                    float e1 = __expf(acc[mt][nt][hf*2 + 1] - gm);
                    acc[mt][nt][hf*2] = e0; acc[mt][nt][hf*2 + 1] = e1;
                    s += e0 + e1;
                }
                s += __shfl_xor_sync(0xffffffffu, s, 1);
                s += __shfl_xor_sync(0xffffffffu, s, 2);
                if ((lane & 3) == 0)
                    red_sum[(warp & 3) * 64 + row] = s;
            }
    }
    __syncthreads();
    {
        #pragma unroll
        for (int mt = 0; mt < 2; ++mt)
            #pragma unroll
            for (int hf = 0; hf < 2; ++hf) {
                const int row = rloc0 + mt*16 + hf*8;
                const float gs = red_sum[row] + red_sum[64 + row] +
                                 red_sum[128 + row] + red_sum[192 + row];
                const float inv = 1.f / gs;
                #pragma unroll
                for (int nt = 0; nt < 8; ++nt) {
                    const uint32_t g = 8 * (warp & 3) + nt;
                    const uint32_t off = row * 512 + ((g << 4) ^ (((uint32_t)(row & 7)) << 4))
                                       + (lane & 3) * 4;
                    *(bf162*)(smraw + 8192 + off) =
                        __floats2bfloat162_rn(acc[mt][nt][hf*2] * inv,
                                              acc[mt][nt][hf*2 + 1] * inv);
                }
            }
    }
    __syncthreads();

    {
        const int wn2 = (warp & 3) * 16;
        float acc2[2][2][4];
        #pragma unroll
        for (int i = 0; i < 2; i++)
            #pragma unroll
            for (int j = 0; j < 2; j++)
                #pragma unroll
                for (int q = 0; q < 4; q++) acc2[i][j][q] = 0.f;

        const uint32_t prow  = pb + (wm + (lane & 15)) * 512;
        const uint32_t vrow0 = vb + (lane & 15) * 128;
        const uint32_t gv = ((uint32_t)(2 * (warp & 3) + (lane >> 4))) << 4;

        #pragma unroll
        for (int ks = 0; ks < 16; ++ks) {
            const uint32_t gp = (uint32_t)((lane >> 4) + ks * 2) << 4;
            unsigned af[2][4];
            ldsm_x4(af[0], prow + (gp ^ xr));
            ldsm_x4(af[1], prow + 16*512 + (gp ^ xr));
            unsigned bq[4];
            ldsm_x4_t(bq, vrow0 + ks*16*128 + (gv ^ xr));
            mma_bf16(acc2[0][0], af[0], bq);
            mma_bf16(acc2[0][1], af[0], bq + 2);
            mma_bf16(acc2[1][0], af[1], bq);
            mma_bf16(acc2[1][1], af[1], bq + 2);
        }
        #pragma unroll
        for (int mt = 0; mt < 2; ++mt)
            #pragma unroll
            for (int nt = 0; nt < 2; ++nt) {
                const int r   = wm + mt*16 + (lane >> 2);
                const int col = wn2 + nt*8 + (lane & 3)*2;
                *(bf162*)(AO + qbase + (size_t)r * 1024 + col) =
                    __floats2bfloat162_rn(acc2[mt][nt][0], acc2[mt][nt][1]);
                *(bf162*)(AO + qbase + (size_t)(r + 8) * 1024 + col) =
                    __floats2bfloat162_rn(acc2[mt][nt][2], acc2[mt][nt][3]);
            }
    }
}

// ---------------------------------------------------------------------------
extern "C" void kernel_launch(void* const* d_in, const int* in_sizes, int n_in,
                              void* d_out, int out_size)
{
    const float* h  = (const float*)d_in[0];
    const float* e  = (const float*)d_in[1];
    const float* g  = (const float*)d_in[2];
    const float* Wq = (const float*)d_in[3];
    const float* bq = (const float*)d_in[4];
    const float* Wk = (const float*)d_in[5];
    const float* bk = (const float*)d_in[6];
    const float* Wv = (const float*)d_in[7];
    const float* bv = (const float*)d_in[8];
    const float* Wo = (const float*)d_in[9];
    const float* bo = (const float*)d_in[10];
    float* out = (float*)d_out;

    cudaFuncSetAttribute(attn_bf16, cudaFuncAttributeMaxDynamicSharedMemorySize, ATTN_SMEM_BYTES);
    cudaFuncSetAttribute(gemm_512,  cudaFuncAttributeMaxDynamicSharedMemorySize, GEMM_SMEM);
    cudaFuncSetAttribute(gemm_256,  cudaFuncAttributeMaxDynamicSharedMemorySize, GEMM_SMEM);

    void *p_ebf, *p_wq, *p_wkv, *p_wo, *p_hn, *p_q, *p_k, *p_v, *p_ao;
    cudaGetSymbolAddress(&p_ebf, g_ebf);
    cudaGetSymbolAddress(&p_wq,  g_wqt);
    cudaGetSymbolAddress(&p_wkv, g_wkv);
    cudaGetSymbolAddress(&p_wo,  g_wot);
    cudaGetSymbolAddress(&p_hn,  g_hnb);
    cudaGetSymbolAddress(&p_q,   g_qb);
    cudaGetSymbolAddress(&p_k,   g_kb);
    cudaGetSymbolAddress(&p_v,   g_vb);
    cudaGetSymbolAddress(&p_ao,  g_aob);

    static cudaStream_t s_h = nullptr;
    static cudaEvent_t evF = nullptr, evW = nullptr, evQ = nullptr, evP = nullptr;
    if (s_h == nullptr) {
        cudaStreamCreateWithFlags(&s_h, cudaStreamNonBlocking);
        cudaEventCreateWithFlags(&evF, cudaEventDisableTiming);
        cudaEventCreateWithFlags(&evW, cudaEventDisableTiming);
        cudaEventCreateWithFlags(&evQ, cudaEventDisableTiming);
        cudaEventCreateWithFlags(&evP, cudaEventDisableTiming);
    }

    // ---- fork ----
    cudaEventRecord(evF, 0);
    cudaStreamWaitEvent(s_h, evF, 0);

    // main stream: full e-convert (critical path)
    f2bf<<<16384, 256>>>((const float4*)e, (bf162*)p_ebf, 4194304);

    // side stream: weight prep + h-chain; prefix after evQ
    f2bf_T4<<<dim3(32, 32, 4), 256, 0, s_h>>>(Wk, Wv, Wq, Wo,
                                              (bf16*)p_wkv, (bf16*)p_wkv + 1024*1024,
                                              (bf16*)p_wq, (bf16*)p_wo);
    cudaEventRecord(evW, s_h);
    rmsnorm_bf16<<<4096, 256, 0, s_h>>>(h, g, (bf16*)p_hn);
    gemm_256<<<dim3(4, 32), 256, GEMM_SMEM, s_h>>>((const bf16*)p_hn, (const bf16*)p_wq,
                                                   bq, (bf16*)p_q, nullptr, nullptr, 0);
    cudaEventRecord(evQ, s_h);
    copy_prefix<<<252, 256, 0, s_h>>>((const float4*)h, (float4*)out);
    cudaEventRecord(evP, s_h);

    // main stream: single fused K+V projection (1024 blocks, throughput GEMM)
    cudaStreamWaitEvent(0, evW, 0);
    gemm_512<<<dim3(8, 128), 512, GEMM_SMEM>>>((const bf16*)p_ebf, (const bf16*)p_wkv,
                                               bk, bv, (bf16*)p_k, (bf16*)p_v);

    // tail: attention (3 CTA/SM) then O-proj (latency GEMM, fused residual)
    cudaStreamWaitEvent(0, evQ, 0);
    attn_bf16<<<1024, 256, ATTN_SMEM_BYTES>>>((const bf16*)p_q, (const bf16*)p_k,
                                              (const bf16*)p_v, (bf16*)p_ao);
    gemm_256<<<dim3(4, 32), 256, GEMM_SMEM>>>((const bf16*)p_ao, (const bf16*)p_wo,
                                              bo, nullptr, out, h, 1);
    cudaStreamWaitEvent(0, evP, 0);   // join side branch
}

// round 17
// speedup vs baseline: 1.0252x; 1.0252x over previous
#include <cuda_runtime.h>
#include <cuda_bf16.h>
#include <math.h>
#include <stdint.h>

// ---------------------------------------------------------------------------
// ChunkedCrossAttention (B=4,S=1024,D=1024,H=16,Dk=64,CL=64,N=2,NL=128)
// Wave-exact KV split (592+432 blocks) + attn/O of batches 0,1 backfilling
// KV part1's drain waves. 512-thr throughput GEMM (KV), 256-thr 64x64-tile
// GEMM (Q/O). Residual fused in O epilogue; prefix off critical path.
// ---------------------------------------------------------------------------

typedef __nv_bfloat16  bf16;
typedef __nv_bfloat162 bf162;

__device__ bf16 g_ebf[16u*1024*1024];
__device__ bf16 g_wqt[1024*1024];          // [n][k]
__device__ bf16 g_wkv[2u*1024*1024];       // [n][k]: rows 0-1023 Wk^T, 1024-2047 Wv^T
__device__ bf16 g_wot[1024*1024];          // [n][k]
__device__ bf16 g_hnb[4u*1024*1024];
__device__ bf16 g_qb [4u*1024*1024];
__device__ bf16 g_kb [16u*1024*1024];
__device__ bf16 g_vb [16u*1024*1024];
__device__ bf16 g_aob[4u*1024*1024];

__device__ __forceinline__ unsigned smaddr(const void* p) {
    return (unsigned)__cvta_generic_to_shared(p);
}
__device__ __forceinline__ void cp16(uint32_t dst, const void* src) {
    asm volatile("cp.async.cg.shared.global [%0], [%1], 16;" :: "r"(dst), "l"(src));
}
#define CP_COMMIT() asm volatile("cp.async.commit_group;" ::: "memory")
#define CP_WAIT(n)  asm volatile("cp.async.wait_group %0;" :: "n"(n) : "memory")

__device__ __forceinline__ void ldsm_x4(unsigned* r, unsigned addr) {
    asm volatile("ldmatrix.sync.aligned.m8n8.x4.shared.b16 {%0,%1,%2,%3}, [%4];"
        : "=r"(r[0]), "=r"(r[1]), "=r"(r[2]), "=r"(r[3]) : "r"(addr));
}
__device__ __forceinline__ void ldsm_x4_t(unsigned* r, unsigned addr) {
    asm volatile("ldmatrix.sync.aligned.m8n8.x4.trans.shared.b16 {%0,%1,%2,%3}, [%4];"
        : "=r"(r[0]), "=r"(r[1]), "=r"(r[2]), "=r"(r[3]) : "r"(addr));
}
__device__ __forceinline__ void mma_bf16(float* c, const unsigned* a, const unsigned* b) {
    asm volatile(
        "mma.sync.aligned.m16n8k16.row.col.f32.bf16.bf16.f32 "
        "{%0,%1,%2,%3}, {%4,%5,%6,%7}, {%8,%9}, {%0,%1,%2,%3};\n"
        : "+f"(c[0]), "+f"(c[1]), "+f"(c[2]), "+f"(c[3])
        : "r"(a[0]), "r"(a[1]), "r"(a[2]), "r"(a[3]), "r"(b[0]), "r"(b[1]));
}

// ---------------------------------------------------------------------------
__global__ __launch_bounds__(256)
void f2bf(const float4* __restrict__ src, bf162* __restrict__ dst, int n4)
{
    int i = blockIdx.x * blockDim.x + threadIdx.x;
    if (i < n4) {
        float4 v = src[i];
        dst[2*i]     = __floats2bfloat162_rn(v.x, v.y);
        dst[2*i + 1] = __floats2bfloat162_rn(v.z, v.w);
    }
}

__global__ __launch_bounds__(256)
void f2bf_T4(const float* __restrict__ W0, const float* __restrict__ W1,
             const float* __restrict__ W2, const float* __restrict__ W3,
             bf16* __restrict__ D0, bf16* __restrict__ D1,
             bf16* __restrict__ D2, bf16* __restrict__ D3)
{
    const float* W; bf16* D;
    switch (blockIdx.z) {
        case 0:  W = W0; D = D0; break;
        case 1:  W = W1; D = D1; break;
        case 2:  W = W2; D = D2; break;
        default: W = W3; D = D3; break;
    }
    __shared__ float t[32][33];
    const int tx = threadIdx.x & 31, ty = threadIdx.x >> 5;
    const int n0 = blockIdx.x * 32, k0 = blockIdx.y * 32;
    #pragma unroll
    for (int i = 0; i < 4; ++i)
        t[ty + 8*i][tx] = W[(size_t)(k0 + ty + 8*i) * 1024 + n0 + tx];
    __syncthreads();
    #pragma unroll
    for (int i = 0; i < 4; ++i)
        D[(size_t)(n0 + ty + 8*i) * 1024 + k0 + tx] = __float2bfloat16(t[tx][ty + 8*i]);
}

__global__ __launch_bounds__(256)
void copy_prefix(const float4* __restrict__ h, float4* __restrict__ out)
{
    int i = blockIdx.x * blockDim.x + threadIdx.x;
    if (i < 4 * 16128) {
        int b = i / 16128, r = i - b * 16128;
        out[(size_t)b * 262144 + r] = h[(size_t)b * 262144 + r];
    }
}

// ---------------------------------------------------------------------------
__global__ __launch_bounds__(256)
void rmsnorm_bf16(const float* __restrict__ h, const float* __restrict__ g,
                  bf16* __restrict__ hn)
{
    const int row = blockIdx.x;
    const int b = row >> 10, p = row & 1023;
    const int t = threadIdx.x;
    bf162* dst = reinterpret_cast<bf162*>(hn + (size_t)row * 1024);
    if (p >= 961) {
        bf162 z = __floats2bfloat162_rn(0.f, 0.f);
        dst[2*t] = z; dst[2*t + 1] = z;
        return;
    }
    const float4* src = reinterpret_cast<const float4*>(h + ((size_t)(b*1024 + p + 63)) * 1024);
    float4 x = src[t];
    float s = x.x*x.x + x.y*x.y + x.z*x.z + x.w*x.w;
    #pragma unroll
    for (int o = 16; o; o >>= 1) s += __shfl_xor_sync(0xffffffffu, s, o);
    __shared__ float red[8];
    if ((t & 31) == 0) red[t >> 5] = s;
    __syncthreads();
    float total = red[0]+red[1]+red[2]+red[3]+red[4]+red[5]+red[6]+red[7];
    float inv = rsqrtf(total * (1.f/1024.f) + 1e-8f);
    float4 gg = reinterpret_cast<const float4*>(g)[t];
    dst[2*t]     = __floats2bfloat162_rn(x.x*gg.x*inv, x.y*gg.y*inv);
    dst[2*t + 1] = __floats2bfloat162_rn(x.z*gg.z*inv, x.w*gg.w*inv);
}

// ---------------------------------------------------------------------------
// Throughput GEMM (KV): 512 thr = 16 warps (4m x 4n), warp tile 32x64.
// Block 128x256, BK=32, 6-stage cp.async ring. mOff selects M range.
// ---------------------------------------------------------------------------
#define GEMM_SMEM (6 * 24576)

__global__ __launch_bounds__(512, 1)
void gemm_512(const bf16* __restrict__ A, const bf16* __restrict__ Bt,
              const float* __restrict__ bias1, const float* __restrict__ bias2,
              bf16* __restrict__ C1, bf16* __restrict__ C2, int mOff)
{
    extern __shared__ char dyn[];
    const uint32_t sbase = smaddr(dyn);

    const int tid = threadIdx.x, lane = tid & 31, warp = tid >> 5;
    const int bm = mOff + blockIdx.y * 128, bn = blockIdx.x * 256;
    const int wm = (warp >> 2) * 32, wn = (warp & 3) * 64;

    const uint32_t ar = tid >> 2, ag = tid & 3;
    const uint32_t aoff = ar * 64 + ((ag ^ ((ar >> 1) & 3)) << 4);
    const bf16* asrc = A + (size_t)(bm + ar) * 1024 + ag * 8;
    uint32_t boff[2]; const bf16* bsrc[2];
    #pragma unroll
    for (int i = 0; i < 2; ++i) {
        uint32_t c = tid + i * 512, r = c >> 2, g = c & 3;
        boff[i] = 8192 + r * 64 + ((g ^ ((r >> 1) & 3)) << 4);
        bsrc[i] = Bt + (size_t)(bn + r) * 1024 + g * 8;
    }

    const uint32_t a_row = wm + (lane & 15);
    const uint32_t a_base = sbase + a_row * 64;
    const uint32_t a_sw = (a_row >> 1) & 3;
    const uint32_t ga0 = lane >> 4;
    const uint32_t b_row = wn + (lane & 7) + ((lane >> 4) & 1) * 8;
    const uint32_t b_base = sbase + 8192 + b_row * 64;
    const uint32_t b_sw = (b_row >> 1) & 3;
    const uint32_t gb0 = (lane >> 3) & 1;

    float acc[2][8][4];
    #pragma unroll
    for (int a = 0; a < 2; ++a)
        #pragma unroll
        for (int b = 0; b < 8; ++b)
            #pragma unroll
            for (int q = 0; q < 4; ++q) acc[a][b][q] = 0.f;

#define LOAD_STAGE(S, KT) do { \
    cp16(sbase + (uint32_t)(S)*24576u + aoff,    asrc    + (KT)*32); \
    cp16(sbase + (uint32_t)(S)*24576u + boff[0], bsrc[0] + (KT)*32); \
    cp16(sbase + (uint32_t)(S)*24576u + boff[1], bsrc[1] + (KT)*32); \
    CP_COMMIT(); \
} while(0)

#define COMPUTE_STAGE(S) do { \
    const uint32_t _ab = a_base + (uint32_t)(S)*24576u; \
    const uint32_t _bb = b_base + (uint32_t)(S)*24576u; \
    _Pragma("unroll") \
    for (int ks = 0; ks < 2; ++ks) { \
        unsigned af[2][4]; \
        _Pragma("unroll") \
        for (int mt = 0; mt < 2; ++mt) \
            ldsm_x4(af[mt], _ab + mt*1024 + (((ga0 + ks*2) ^ a_sw) << 4)); \
        unsigned bq[4][4]; \
        _Pragma("unroll") \
        for (int nt = 0; nt < 4; ++nt) \
            ldsm_x4(bq[nt], _bb + nt*1024 + (((gb0 + ks*2) ^ b_sw) << 4)); \
        _Pragma("unroll") \
        for (int mt = 0; mt < 2; ++mt) \
            _Pragma("unroll") \
            for (int nt = 0; nt < 4; ++nt) { \
                mma_bf16(acc[mt][nt*2],     af[mt], bq[nt]); \
                mma_bf16(acc[mt][nt*2 + 1], af[mt], bq[nt] + 2); \
            } \
    } \
} while(0)

    #pragma unroll
    for (int s = 0; s < 4; ++s) LOAD_STAGE(s, s);

    int s0 = 0;
    for (int kt = 0; kt < 32; kt += 2) {
        if (kt < 30) { CP_WAIT(2); } else { CP_WAIT(0); }
        __syncthreads();
        const int s1 = (s0 + 1 == 6) ? 0 : s0 + 1;
        COMPUTE_STAGE(s0);
        COMPUTE_STAGE(s1);
        if (kt + 4 < 32) {
            int s4 = s0 + 4; if (s4 >= 6) s4 -= 6;
            LOAD_STAGE(s4, kt + 4);
        }
        if (kt + 5 < 32) {
            int s5 = s0 + 5; if (s5 >= 6) s5 -= 6;
            LOAD_STAGE(s5, kt + 5);
        }
        s0 += 2; if (s0 >= 6) s0 -= 6;
    }

    #pragma unroll
    for (int mt = 0; mt < 2; ++mt) {
        #pragma unroll
        for (int j = 0; j < 8; ++j) {
            const int row  = bm + wm + mt * 16 + (lane >> 2);
            const int gcol = bn + wn + (j >> 1) * 16 + (j & 1) * 8 + (lane & 3) * 2;
            const float* bb = bias1; bf16* dst = C1; int cc = gcol;
            if (gcol >= 1024) { bb = bias2; dst = C2; cc = gcol - 1024; }
            const float b0 = bb[cc], b1 = bb[cc + 1];
            *(bf162*)(dst + (size_t)row * 1024 + cc) =
                __floats2bfloat162_rn(acc[mt][j][0] + b0, acc[mt][j][1] + b1);
            *(bf162*)(dst + (size_t)(row + 8) * 1024 + cc) =
                __floats2bfloat162_rn(acc[mt][j][2] + b0, acc[mt][j][3] + b1);
        }
    }
#undef LOAD_STAGE
#undef COMPUTE_STAGE
}

// ---------------------------------------------------------------------------
// Latency GEMM (Q, O): 256 thr = 8 warps (2m x 4n), warp tile 64x64.
// mode 0: bf16 store; mode 1: residual write Cf[row+63]=Hres+acc+bias1.
// ---------------------------------------------------------------------------
__global__ __launch_bounds__(256, 1)
void gemm_256(const bf16* __restrict__ A, const bf16* __restrict__ Bt,
              const float* __restrict__ bias1,
              bf16* __restrict__ C1,
              float* __restrict__ Cf, const float* __restrict__ Hres,
              int mode, int mOff)
{
    extern __shared__ char dyn[];
    const uint32_t sbase = smaddr(dyn);

    const int tid = threadIdx.x, lane = tid & 31, warp = tid >> 5;
    const int bm = mOff + blockIdx.y * 128, bn = blockIdx.x * 256;
    const int wm = (warp >> 2) * 64, wn = (warp & 3) * 64;

    uint32_t aoff[2]; const bf16* asrc[2];
    #pragma unroll
    for (int i = 0; i < 2; ++i) {
        uint32_t c = tid + i * 256, r = c >> 2, g = c & 3;
        aoff[i] = r * 64 + ((g ^ ((r >> 1) & 3)) << 4);
        asrc[i] = A + (size_t)(bm + r) * 1024 + g * 8;
    }
    uint32_t boff[4]; const bf16* bsrc[4];
    #pragma unroll
    for (int i = 0; i < 4; ++i) {
        uint32_t c = tid + i * 256, r = c >> 2, g = c & 3;
        boff[i] = 8192 + r * 64 + ((g ^ ((r >> 1) & 3)) << 4);
        bsrc[i] = Bt + (size_t)(bn + r) * 1024 + g * 8;
    }

    const uint32_t a_row = wm + (lane & 15);
    const uint32_t a_base = sbase + a_row * 64;
    const uint32_t a_sw = (a_row >> 1) & 3;
    const uint32_t ga0 = lane >> 4;
    const uint32_t b_row = wn + (lane & 7) + ((lane >> 4) & 1) * 8;
    const uint32_t b_base = sbase + 8192 + b_row * 64;
    const uint32_t b_sw = (b_row >> 1) & 3;
    const uint32_t gb0 = (lane >> 3) & 1;

    float acc[4][8][4];
    #pragma unroll
    for (int a = 0; a < 4; ++a)
        #pragma unroll
        for (int b = 0; b < 8; ++b)
            #pragma unroll
            for (int q = 0; q < 4; ++q) acc[a][b][q] = 0.f;

#define LOAD_STAGE(S, KT) do { \
    cp16(sbase + (uint32_t)(S)*24576u + aoff[0], asrc[0] + (KT)*32); \
    cp16(sbase + (uint32_t)(S)*24576u + aoff[1], asrc[1] + (KT)*32); \
    cp16(sbase + (uint32_t)(S)*24576u + boff[0], bsrc[0] + (KT)*32); \
    cp16(sbase + (uint32_t)(S)*24576u + boff[1], bsrc[1] + (KT)*32); \
    cp16(sbase + (uint32_t)(S)*24576u + boff[2], bsrc[2] + (KT)*32); \
    cp16(sbase + (uint32_t)(S)*24576u + boff[3], bsrc[3] + (KT)*32); \
    CP_COMMIT(); \
} while(0)

#define COMPUTE_STAGE(S) do { \
    const uint32_t _ab = a_base + (uint32_t)(S)*24576u; \
    const uint32_t _bb = b_base + (uint32_t)(S)*24576u; \
    _Pragma("unroll") \
    for (int ks = 0; ks < 2; ++ks) { \
        unsigned bq[4][4]; \
        _Pragma("unroll") \
        for (int nt = 0; nt < 4; ++nt) \
            ldsm_x4(bq[nt], _bb + nt*1024 + (((gb0 + ks*2) ^ b_sw) << 4)); \
        _Pragma("unroll") \
        for (int mt = 0; mt < 4; ++mt) { \
            unsigned af[4]; \
            ldsm_x4(af, _ab + mt*1024 + (((ga0 + ks*2) ^ a_sw) << 4)); \
            _Pragma("unroll") \
            for (int nt = 0; nt < 4; ++nt) { \
                mma_bf16(acc[mt][nt*2],     af, bq[nt]); \
                mma_bf16(acc[mt][nt*2 + 1], af, bq[nt] + 2); \
            } \
        } \
    } \
} while(0)

    #pragma unroll
    for (int s = 0; s < 4; ++s) LOAD_STAGE(s, s);

    int s0 = 0;
    for (int kt = 0; kt < 32; kt += 2) {
        if (kt < 30) { CP_WAIT(2); } else { CP_WAIT(0); }
        __syncthreads();
        const int s1 = (s0 + 1 == 6) ? 0 : s0 + 1;
        COMPUTE_STAGE(s0);
        COMPUTE_STAGE(s1);
        if (kt + 4 < 32) {
            int s4 = s0 + 4; if (s4 >= 6) s4 -= 6;
            LOAD_STAGE(s4, kt + 4);
        }
        if (kt + 5 < 32) {
            int s5 = s0 + 5; if (s5 >= 6) s5 -= 6;
            LOAD_STAGE(s5, kt + 5);
        }
        s0 += 2; if (s0 >= 6) s0 -= 6;
    }

    #pragma unroll
    for (int mt = 0; mt < 4; ++mt) {
        #pragma unroll
        for (int j = 0; j < 8; ++j) {
            const int row  = bm + wm + mt * 16 + (lane >> 2);
            const int gcol = bn + wn + (j >> 1) * 16 + (j & 1) * 8 + (lane & 3) * 2;
            if (mode == 0) {
                const float b0 = bias1[gcol], b1 = bias1[gcol + 1];
                *(bf162*)(C1 + (size_t)row * 1024 + gcol) =
                    __floats2bfloat162_rn(acc[mt][j][0] + b0, acc[mt][j][1] + b1);
                *(bf162*)(C1 + (size_t)(row + 8) * 1024 + gcol) =
                    __floats2bfloat162_rn(acc[mt][j][2] + b0, acc[mt][j][3] + b1);
            } else {
                const float b0 = bias1[gcol], b1 = bias1[gcol + 1];
                const int p = row & 1023;
                if (p < 961) {
                    const size_t o = (size_t)(row + 63) * 1024 + gcol;
                    Cf[o]     = Hres[o]     + acc[mt][j][0] + b0;
                    Cf[o + 1] = Hres[o + 1] + acc[mt][j][1] + b1;
                }
                const int p2 = (row + 8) & 1023;
                if (p2 < 961) {
                    const size_t o = (size_t)(row + 71) * 1024 + gcol;
                    Cf[o]     = Hres[o]     + acc[mt][j][2] + b0;
                    Cf[o + 1] = Hres[o + 1] + acc[mt][j][3] + b1;
                }
            }
        }
    }
#undef LOAD_STAGE
#undef COMPUTE_STAGE
}

// ---------------------------------------------------------------------------
// Attention per (b, chunk, head): 256 threads = 8 warps (2m x 4n).
// Register logits + distributed softmax; P overwrites K slot -> 74KB, 3 CTA/SM.
// ---------------------------------------------------------------------------
#define ATTN_SMEM_BYTES 75776

__global__ __launch_bounds__(256, 3)
void attn_bf16(const bf16* __restrict__ Q, const bf16* __restrict__ K,
               const bf16* __restrict__ V, bf16* __restrict__ AO, int bidOff)
{
    extern __shared__ char smraw[];
    const uint32_t sb = smaddr(smraw);
    const uint32_t qb = sb, kb = sb + 8192, vb = sb + 40960, pb = sb + 8192;
    float* red_max = reinterpret_cast<float*>(smraw + 73728);
    float* red_sum = reinterpret_cast<float*>(smraw + 74752);

    const int bid = blockIdx.x + bidOff;
    const int b  = bid >> 8, c = (bid >> 4) & 15, hh = bid & 15;
    const int tid = threadIdx.x, lane = tid & 31, warp = tid >> 5;

    const size_t qbase  = ((size_t)(b * 1024 + c * 64)) * 1024 + hh * 64;
    const size_t kvbase = ((size_t)((b * 16 + c) * 256)) * 1024 + hh * 64;

    #pragma unroll
    for (int i = 0; i < 2; ++i) {
        int ch = tid + i * 256, r = ch >> 3, sg = ch & 7;
        uint32_t off = r * 128 + (((uint32_t)sg << 4) ^ (((uint32_t)(r & 7)) << 4));
        *(uint4*)(smraw + off) = *(const uint4*)(Q + qbase + (size_t)r * 1024 + sg * 8);
    }
    #pragma unroll
    for (int i = 0; i < 8; ++i) {
        int ch = tid + i * 256, r = ch >> 3, sg = ch & 7;
        uint32_t off = r * 128 + (((uint32_t)sg << 4) ^ (((uint32_t)(r & 7)) << 4));
        *(uint4*)(smraw + 8192 + off)  = *(const uint4*)(K + kvbase + (size_t)r * 1024 + sg * 8);
        *(uint4*)(smraw + 40960 + off) = *(const uint4*)(V + kvbase + (size_t)r * 1024 + sg * 8);
    }
    __syncthreads();

    const int wm  = (warp >> 2) * 32;
    const uint32_t xr = ((uint32_t)(lane & 7)) << 4;

    float acc[2][8][4];
    #pragma unroll
    for (int i = 0; i < 2; i++)
        #pragma unroll
        for (int j = 0; j < 8; j++)
            #pragma unroll
            for (int q = 0; q < 4; q++) acc[i][j][q] = 0.f;

    {
        const int wnl = (warp & 3) * 64;
        const uint32_t qrow = qb + (wm + (lane & 15)) * 128;
        const uint32_t krow = kb + (wnl + (lane & 7) + ((lane >> 4) & 1) * 8) * 128;

        #pragma unroll
        for (int ks = 0; ks < 4; ++ks) {
            const uint32_t gq = (uint32_t)((lane >> 4) + ks * 2) << 4;
            unsigned af[2][4];
            ldsm_x4(af[0], qrow + (gq ^ xr));
            ldsm_x4(af[1], qrow + 16*128 + (gq ^ xr));
            const uint32_t gk = (uint32_t)(((lane >> 3) & 1) + ks * 2) << 4;
            #pragma unroll
            for (int nt = 0; nt < 4; ++nt) {
                unsigned bq[4];
                ldsm_x4(bq, krow + nt*16*128 + (gk ^ xr));
                mma_bf16(acc[0][nt*2],     af[0], bq);
                mma_bf16(acc[0][nt*2 + 1], af[0], bq + 2);
                mma_bf16(acc[1][nt*2],     af[1], bq);
                mma_bf16(acc[1][nt*2 + 1], af[1], bq + 2);
            }
        }
    }

    #pragma unroll
    for (int i = 0; i < 2; i++)
        #pragma unroll
        for (int j = 0; j < 8; j++)
            #pragma unroll
            for (int q = 0; q < 4; q++) acc[i][j][q] *= 0.125f;

    const int rloc0 = wm + (lane >> 2);
    {
        #pragma unroll
        for (int mt = 0; mt < 2; ++mt)
            #pragma unroll
            for (int hf = 0; hf < 2; ++hf) {
                float m = -1e30f;
                #pragma unroll
                for (int nt = 0; nt < 8; ++nt)
                    m = fmaxf(m, fmaxf(acc[mt][nt][hf*2], acc[mt][nt][hf*2 + 1]));
                m = fmaxf(m, __shfl_xor_sync(0xffffffffu, m, 1));
                m = fmaxf(m, __shfl_xor_sync(0xffffffffu, m, 2));
                if ((lane & 3) == 0)
                    red_max[(warp & 3) * 64 + rloc0 + mt*16 + hf*8] = m;
            }
    }
    __syncthreads();
    {
        #pragma unroll
        for (int mt = 0; mt < 2; ++mt)
            #pragma unroll
            for (int hf = 0; hf < 2; ++hf) {
                const int row = rloc0 + mt*16 + hf*8;
                const float gm = fmaxf(fmaxf(red_max[row], red_max[64 + row]),
                                       fmaxf(red_max[128 + row], red_max[192 + row]));
                float s = 0.f;
                #pragma unroll
                for (int nt = 0; nt < 8; ++nt) {
                    float e0 = __expf(acc[mt][nt][hf*2]     - gm);
                    float e1 = __expf(acc[mt][nt][hf*2 + 1] - gm);
                    acc[mt][nt][hf*2] = e0; acc[mt][nt][hf*2 + 1] = e1;
                    s += e0 + e1;
                }
                s += __shfl_xor_sync(0xffffffffu, s, 1);
                s += __shfl_xor_sync(0xffffffffu, s, 2);
                if ((lane & 3) == 0)
                    red_sum[(warp & 3) * 64 + row] = s;
            }
    }
    __syncthreads();
    {
        #pragma unroll
        for (int mt = 0; mt < 2; ++mt)
            #pragma unroll
            for (int hf = 0; hf < 2; ++hf) {
                const int row = rloc0 + mt*16 + hf*8;
                const float gs = red_sum[row] + red_sum[64 + row] +
                                 red_sum[128 + row] + red_sum[192 + row];
                const float inv = 1.f / gs;
                #pragma unroll
                for (int nt = 0; nt < 8; ++nt) {
                    const uint32_t g = 8 * (warp & 3) + nt;
                    const uint32_t off = row * 512 + ((g << 4) ^ (((uint32_t)(row & 7)) << 4))
                                       + (lane & 3) * 4;
                    *(bf162*)(smraw + 8192 + off) =
                        __floats2bfloat162_rn(acc[mt][nt][hf*2] * inv,
                                              acc[mt][nt][hf*2 + 1] * inv);
                }
            }
    }
    __syncthreads();

    {
        const int wn2 = (warp & 3) * 16;
        float acc2[2][2][4];
        #pragma unroll
        for (int i = 0; i < 2; i++)
            #pragma unroll
            for (int j = 0; j < 2; j++)
                #pragma unroll
                for (int q = 0; q < 4; q++) acc2[i][j][q] = 0.f;

        const uint32_t prow  = pb + (wm + (lane & 15)) * 512;
        const uint32_t vrow0 = vb + (lane & 15) * 128;
        const uint32_t gv = ((uint32_t)(2 * (warp & 3) + (lane >> 4))) << 4;

        #pragma unroll
        for (int ks = 0; ks < 16; ++ks) {
            const uint32_t gp = (uint32_t)((lane >> 4) + ks * 2) << 4;
            unsigned af[2][4];
            ldsm_x4(af[0], prow + (gp ^ xr));
            ldsm_x4(af[1], prow + 16*512 + (gp ^ xr));
            unsigned bq[4];
            ldsm_x4_t(bq, vrow0 + ks*16*128 + (gv ^ xr));
            mma_bf16(acc2[0][0], af[0], bq);
            mma_bf16(acc2[0][1], af[0], bq + 2);
            mma_bf16(acc2[1][0], af[1], bq);
            mma_bf16(acc2[1][1], af[1], bq + 2);
        }
        #pragma unroll
        for (int mt = 0; mt < 2; ++mt)
            #pragma unroll
            for (int nt = 0; nt < 2; ++nt) {
                const int r   = wm + mt*16 + (lane >> 2);
                const int col = wn2 + nt*8 + (lane & 3)*2;
                *(bf162*)(AO + qbase + (size_t)r * 1024 + col) =
                    __floats2bfloat162_rn(acc2[mt][nt][0], acc2[mt][nt][1]);
                *(bf162*)(AO + qbase + (size_t)(r + 8) * 1024 + col) =
                    __floats2bfloat162_rn(acc2[mt][nt][2], acc2[mt][nt][3]);
            }
    }
}

// ---------------------------------------------------------------------------
extern "C" void kernel_launch(void* const* d_in, const int* in_sizes, int n_in,
                              void* d_out, int out_size)
{
    const float* h  = (const float*)d_in[0];
    const float* e  = (const float*)d_in[1];
    const float* g  = (const float*)d_in[2];
    const float* Wq = (const float*)d_in[3];
    const float* bq = (const float*)d_in[4];
    const float* Wk = (const float*)d_in[5];
    const float* bk = (const float*)d_in[6];
    const float* Wv = (const float*)d_in[7];
    const float* bv = (const float*)d_in[8];
    const float* Wo = (const float*)d_in[9];
    const float* bo = (const float*)d_in[10];
    float* out = (float*)d_out;

    cudaFuncSetAttribute(attn_bf16, cudaFuncAttributeMaxDynamicSharedMemorySize, ATTN_SMEM_BYTES);
    cudaFuncSetAttribute(gemm_512,  cudaFuncAttributeMaxDynamicSharedMemorySize, GEMM_SMEM);
    cudaFuncSetAttribute(gemm_256,  cudaFuncAttributeMaxDynamicSharedMemorySize, GEMM_SMEM);

    void *p_ebf, *p_wq, *p_wkv, *p_wo, *p_hn, *p_q, *p_k, *p_v, *p_ao;
    cudaGetSymbolAddress(&p_ebf, g_ebf);
    cudaGetSymbolAddress(&p_wq,  g_wqt);
    cudaGetSymbolAddress(&p_wkv, g_wkv);
    cudaGetSymbolAddress(&p_wo,  g_wot);
    cudaGetSymbolAddress(&p_hn,  g_hnb);
    cudaGetSymbolAddress(&p_q,   g_qb);
    cudaGetSymbolAddress(&p_k,   g_kb);
    cudaGetSymbolAddress(&p_v,   g_vb);
    cudaGetSymbolAddress(&p_ao,  g_aob);

    static cudaStream_t s_h = nullptr;
    static cudaEvent_t evF = nullptr, evW = nullptr, evE1 = nullptr,
                       evQ = nullptr, evK0 = nullptr, evO01 = nullptr;
    if (s_h == nullptr) {
        cudaStreamCreateWithFlags(&s_h, cudaStreamNonBlocking);
        cudaEventCreateWithFlags(&evF,   cudaEventDisableTiming);
        cudaEventCreateWithFlags(&evW,   cudaEventDisableTiming);
        cudaEventCreateWithFlags(&evE1,  cudaEventDisableTiming);
        cudaEventCreateWithFlags(&evQ,   cudaEventDisableTiming);
        cudaEventCreateWithFlags(&evK0,  cudaEventDisableTiming);
        cudaEventCreateWithFlags(&evO01, cudaEventDisableTiming);
    }

    // wave-exact KV split: part0 rows [0,9472) -> 592 blocks (4.00 waves),
    // part1 rows [9472,16384) -> 432 blocks (2.92 -> 3 waves); total 7 waves.
    const int CH0_F4 = 9472 * 256;
    const int CH1_F4 = 4194304 - CH0_F4;

    // ---- fork ----
    cudaEventRecord(evF, 0);
    cudaStreamWaitEvent(s_h, evF, 0);

    // main: convert e chunk0 (feeds KV part0)
    f2bf<<<(CH0_F4 + 255) / 256, 256>>>((const float4*)e, (bf162*)p_ebf, CH0_F4);

    // side: weight prep, e chunk1 convert, h-chain, prefix
    f2bf_T4<<<dim3(32, 32, 4), 256, 0, s_h>>>(Wk, Wv, Wq, Wo,
                                              (bf16*)p_wkv, (bf16*)p_wkv + 1024*1024,
                                              (bf16*)p_wq, (bf16*)p_wo);
    cudaEventRecord(evW, s_h);
    f2bf<<<(CH1_F4 + 255) / 256, 256, 0, s_h>>>((const float4*)e + CH0_F4,
                                                (bf162*)p_ebf + 2*(size_t)CH0_F4, CH1_F4);
    cudaEventRecord(evE1, s_h);
    rmsnorm_bf16<<<4096, 256, 0, s_h>>>(h, g, (bf16*)p_hn);
    gemm_256<<<dim3(4, 32), 256, GEMM_SMEM, s_h>>>((const bf16*)p_hn, (const bf16*)p_wq,
                                                   bq, (bf16*)p_q, nullptr, nullptr, 0, 0);
    cudaEventRecord(evQ, s_h);
    copy_prefix<<<252, 256, 0, s_h>>>((const float4*)h, (float4*)out);

    // main: KV part0 (batches 0,1 fully covered), then part1
    cudaStreamWaitEvent(0, evW, 0);
    gemm_512<<<dim3(8, 74), 512, GEMM_SMEM>>>((const bf16*)p_ebf, (const bf16*)p_wkv,
                                              bk, bv, (bf16*)p_k, (bf16*)p_v, 0);
    cudaEventRecord(evK0, 0);
    cudaStreamWaitEvent(0, evE1, 0);
    gemm_512<<<dim3(8, 54), 512, GEMM_SMEM>>>((const bf16*)p_ebf, (const bf16*)p_wkv,
                                              bk, bv, (bf16*)p_k, (bf16*)p_v, 9472);

    // side: attn + O for batches 0,1 — blocks backfill KV part1's drain waves
    cudaStreamWaitEvent(s_h, evK0, 0);
    attn_bf16<<<512, 256, ATTN_SMEM_BYTES, s_h>>>((const bf16*)p_q, (const bf16*)p_k,
                                                  (const bf16*)p_v, (bf16*)p_ao, 0);
    gemm_256<<<dim3(4, 16), 256, GEMM_SMEM, s_h>>>((const bf16*)p_ao, (const bf16*)p_wo,
                                                   bo, nullptr, out, h, 1, 0);
    cudaEventRecord(evO01, s_h);

    // main: attn + O for batches 2,3; join
    cudaStreamWaitEvent(0, evQ, 0);
    attn_bf16<<<512, 256, ATTN_SMEM_BYTES>>>((const bf16*)p_q, (const bf16*)p_k,
                                             (const bf16*)p_v, (bf16*)p_ao, 512);
    gemm_256<<<dim3(4, 16), 256, GEMM_SMEM>>>((const bf16*)p_ao, (const bf16*)p_wo,
                                              bo, nullptr, out, h, 1, 2048);
    cudaStreamWaitEvent(0, evO01, 0);
}